// round 7
// baseline (speedup 1.0000x reference)
#include <cuda_runtime.h>

#define L1D 16
#define IN_DIM 128
#define MAXN 51200
#define ZST 132        // padded smem row stride (floats) in node MLP
#define NB1 48         // nodes per block, kernel 1 (192 threads)
#define NB2 32         // nodes per tile, kernel 2
#define MAXG 10240000  // capacity of each G table (floats)

// Scratch (allowed: __device__ globals)
__device__ __align__(16) float g_h1[MAXN * L1D];
__device__ __align__(16) float g_h2[MAXN * L1D];
__device__ float g_G1[MAXG];
__device__ float g_G2[MAXG];

// packed f32x2 fma: d = a*b + d (elementwise on two packed floats)
__device__ __forceinline__ void fma_f32x2(unsigned long long& d,
                                          unsigned long long a,
                                          unsigned long long b) {
    asm("fma.rn.f32x2 %0, %1, %2, %0;" : "+l"(d) : "l"(a), "l"(b));
}
__device__ __forceinline__ unsigned long long pack2(float lo, float hi) {
    unsigned long long r;
    asm("mov.b64 %0, {%1, %2};" : "=l"(r) : "f"(lo), "f"(hi));
    return r;
}
__device__ __forceinline__ float unpack_sum(unsigned long long v) {
    float lo = __uint_as_float((unsigned)(v & 0xFFFFFFFFu));
    float hi = __uint_as_float((unsigned)(v >> 32));
    return lo + hi;
}

// ---------------------------------------------------------------------------
// Kernel 1: per-node tiny MLP.  h1 = relu(z @ w1_l1), h2 = relu(z @ w2_l1)
// 192 threads, 48 nodes/block. Thread = (col, 4-node group). Weights
// transposed col-major in padded smem; float4 LDS throughout.
// Static smem: 48*132*4 + 2*16*132*4 = 42240 B (< 48 KB limit).
// ---------------------------------------------------------------------------
__global__ __launch_bounds__(192) void node_mlp_kernel(
    const float* __restrict__ z,
    const float* __restrict__ w1,
    const float* __restrict__ w2,
    int n_nodes)
{
    __shared__ float zs[NB1 * ZST];      // 25344 B
    __shared__ float w1T[L1D * ZST];     // [col][k], 8448 B
    __shared__ float w2T[L1D * ZST];

    const int tid = threadIdx.x;
    const int nbase = blockIdx.x * NB1;

    for (int i = tid; i < IN_DIM * L1D; i += 192) {
        int k = i >> 4, c = i & 15;
        w1T[c * ZST + k] = w1[i];
        w2T[c * ZST + k] = w2[i];
    }
    {
        const float4* z4 = (const float4*)(z + (size_t)nbase * IN_DIM);
        int nval = n_nodes - nbase; if (nval > NB1) nval = NB1;
        for (int i = tid; i < nval * (IN_DIM / 4); i += 192) {
            int r = i >> 5, q = i & 31;
            *(float4*)(zs + r * ZST + q * 4) = z4[i];
        }
    }
    __syncthreads();

    const int col = tid & 15;
    const int grp = tid >> 4;            // 0..11 -> nodes grp*4 .. grp*4+3

    unsigned long long a1[4][2] = {}, a2[4][2] = {};

    #pragma unroll 4
    for (int k = 0; k < IN_DIM; k += 4) {
        ulonglong2 wa = *(const ulonglong2*)(w1T + col * ZST + k);
        ulonglong2 wb = *(const ulonglong2*)(w2T + col * ZST + k);
        #pragma unroll
        for (int j = 0; j < 4; j++) {
            ulonglong2 zv = *(const ulonglong2*)(zs + (grp * 4 + j) * ZST + k);
            fma_f32x2(a1[j][0], zv.x, wa.x);
            fma_f32x2(a1[j][1], zv.y, wa.y);
            fma_f32x2(a2[j][0], zv.x, wb.x);
            fma_f32x2(a2[j][1], zv.y, wb.y);
        }
    }

    #pragma unroll
    for (int j = 0; j < 4; j++) {
        int node = nbase + grp * 4 + j;
        if (node < n_nodes) {
            g_h1[node * L1D + col] = fmaxf(unpack_sum(a1[j][0]) + unpack_sum(a1[j][1]), 0.f);
            g_h2[node * L1D + col] = fmaxf(unpack_sum(a2[j][0]) + unpack_sum(a2[j][1]), 0.f);
        }
    }
}

// ---------------------------------------------------------------------------
// Kernel 2: G tables.  G1[n][t] = dot(h1[n], w1_l2[t]),  G2 likewise.
// Persistent grid (148 blocks): weight tables staged ONCE per block into
// smem as packed f32-pairs [c2][t] (consecutive-lane LDS.64, conflict-free),
// then loop over 32-node tiles. Warp = 4 nodes, h packed in registers,
// lane = type, all math fma.rn.f32x2.
// ---------------------------------------------------------------------------
__global__ __launch_bounds__(256, 1) void gcompute_kernel(
    const float* __restrict__ w1l2,
    const float* __restrict__ w2l2,
    int n_nodes, int n_etype)
{
    extern __shared__ unsigned long long wp[];   // [2][8][n_etype]
    unsigned long long* wp1 = wp;
    unsigned long long* wp2 = wp + 8 * n_etype;

    const int tid = threadIdx.x;
    {
        const float2* s1 = (const float2*)w1l2;
        const float2* s2 = (const float2*)w2l2;
        for (int i = tid; i < n_etype * 8; i += 256) {
            int t = i >> 3, c2 = i & 7;
            float2 v1 = s1[i], v2 = s2[i];
            wp1[c2 * n_etype + t] = pack2(v1.x, v1.y);
            wp2[c2 * n_etype + t] = pack2(v2.x, v2.y);
        }
    }
    __syncthreads();

    const int warp = tid >> 5, lane = tid & 31;
    const int ntiles = (n_nodes + NB2 - 1) / NB2;
    const unsigned long long* h1p = (const unsigned long long*)g_h1;
    const unsigned long long* h2p = (const unsigned long long*)g_h2;

    for (int tile = blockIdx.x; tile < ntiles; tile += gridDim.x) {
        const int n0 = tile * NB2 + warp * 4;

        unsigned long long hp1[4][8], hp2[4][8];
        #pragma unroll
        for (int j = 0; j < 4; j++) {
            int n = n0 + j; if (n >= n_nodes) n = n_nodes - 1;
            #pragma unroll
            for (int c2 = 0; c2 < 8; c2++) {
                hp1[j][c2] = h1p[n * 8 + c2];
                hp2[j][c2] = h2p[n * 8 + c2];
            }
        }

        for (int t = lane; t < n_etype; t += 32) {
            unsigned long long acc1[4] = {}, acc2[4] = {};
            #pragma unroll
            for (int c2 = 0; c2 < 8; c2++) {
                unsigned long long w1v = wp1[c2 * n_etype + t];
                unsigned long long w2v = wp2[c2 * n_etype + t];
                #pragma unroll
                for (int j = 0; j < 4; j++) {
                    fma_f32x2(acc1[j], hp1[j][c2], w1v);
                    fma_f32x2(acc2[j], hp2[j][c2], w2v);
                }
            }
            #pragma unroll
            for (int j = 0; j < 4; j++) {
                int n = n0 + j;
                if (n < n_nodes) {
                    g_G1[(size_t)n * n_etype + t] = unpack_sum(acc1[j]);
                    g_G2[(size_t)n * n_etype + t] = unpack_sum(acc2[j]);
                }
            }
        }
    }
}

// ---------------------------------------------------------------------------
// Kernel 3: per-edge scoring. 1 thread per edge, 4 edges/thread batched.
//   out[e] = sigmoid(G1[s*ne+t] + G2[d*ne+t])
// Inline int64/int32 detection per block prologue.
// ---------------------------------------------------------------------------
__global__ __launch_bounds__(256) void edge_kernel(
    const void* __restrict__ ei,
    const void* __restrict__ et,
    float* __restrict__ out,
    int n_edges, int n_etype)
{
    __shared__ int s_is64;
    if (threadIdx.x < 32) {
        unsigned v = ((const unsigned*)ei)[2 * threadIdx.x + 1];
        unsigned any = __ballot_sync(0xFFFFFFFFu, v != 0u);
        if (threadIdx.x == 0) s_is64 = (any == 0u) ? 1 : 0;
    }
    __syncthreads();
    const int is64 = s_is64;

    const int T = gridDim.x * blockDim.x;
    const int tid0 = blockIdx.x * blockDim.x + threadIdx.x;
    const int emax = n_edges - 1;

    const long long* p64 = (const long long*)ei;
    const int*       p32 = (const int*)ei;
    const long long* t64 = (const long long*)et;
    const int*       t32 = (const int*)et;

    int s[4], d[4], t[4], e[4];
    #pragma unroll
    for (int i = 0; i < 4; i++) {
        e[i] = tid0 + i * T;
        int ec = e[i] < n_edges ? e[i] : emax;
        if (is64) {
            s[i] = (int)__ldg(p64 + ec);
            d[i] = (int)__ldg(p64 + (size_t)n_edges + ec);
            t[i] = (int)__ldg(t64 + ec);
        } else {
            s[i] = __ldg(p32 + ec);
            d[i] = __ldg(p32 + (size_t)n_edges + ec);
            t[i] = __ldg(t32 + ec);
        }
    }
    float v1[4], v2[4];
    #pragma unroll
    for (int i = 0; i < 4; i++) {
        v1[i] = __ldg(g_G1 + (size_t)s[i] * n_etype + t[i]);
        v2[i] = __ldg(g_G2 + (size_t)d[i] * n_etype + t[i]);
    }
    #pragma unroll
    for (int i = 0; i < 4; i++) {
        if (e[i] < n_edges)
            out[e[i]] = 1.f / (1.f + __expf(-(v1[i] + v2[i])));
    }
}

// ---------------------------------------------------------------------------
// Launch. Inputs (metadata order): z, w1_l1, w1_l2, w2_l1, w2_l2,
// edge_index [2,E], edge_type [E].  Output: float32 [E].
// ---------------------------------------------------------------------------
extern "C" void kernel_launch(void* const* d_in, const int* in_sizes, int n_in,
                              void* d_out, int out_size) {
    const float* z     = (const float*)d_in[0];
    const float* w1_l1 = (const float*)d_in[1];
    const float* w1_l2 = (const float*)d_in[2];
    const float* w2_l1 = (const float*)d_in[3];
    const float* w2_l2 = (const float*)d_in[4];
    const void*  ei    = d_in[5];
    const void*  et    = d_in[6];
    float* out = (float*)d_out;

    int n_nodes = in_sizes[0] / IN_DIM;
    int n_etype = in_sizes[2] / L1D;
    int n_edges = out_size;

    int nb1 = (n_nodes + NB1 - 1) / NB1;
    node_mlp_kernel<<<nb1, 192>>>(z, w1_l1, w2_l1, n_nodes);

    size_t smem2 = (size_t)2 * 8 * n_etype * sizeof(unsigned long long);
    gcompute_kernel<<<148, 256, smem2>>>(w1_l2, w2_l2, n_nodes, n_etype);

    int nb3 = (n_edges + 1024 - 1) / 1024;
    edge_kernel<<<nb3, 256>>>(ei, et, out, n_edges, n_etype);
}

// round 8
// speedup vs baseline: 1.4283x; 1.4283x over previous
#include <cuda_runtime.h>
#include <cuda_fp16.h>

#define L1D 16
#define IN_DIM 128
#define MAXN 65536
#define WSTRIDE 20   // padded smem row stride (floats) for edge weight tables
#define ZST 132      // padded smem row stride in node MLP
#define NPB 32       // nodes per block in node_mlp

// Scratch: node hidden activations in fp16 (allowed: __device__ globals)
__device__ __align__(16) __half g_h1h[MAXN * L1D];
__device__ __align__(16) __half g_h2h[MAXN * L1D];

// packed f32x2 fma: d = a*b + d
__device__ __forceinline__ void fma_f32x2(unsigned long long& d,
                                          unsigned long long a,
                                          unsigned long long b) {
    asm("fma.rn.f32x2 %0, %1, %2, %0;" : "+l"(d) : "l"(a), "l"(b));
}
__device__ __forceinline__ float unpack_sum(unsigned long long v) {
    float lo = __uint_as_float((unsigned)(v & 0xFFFFFFFFu));
    float hi = __uint_as_float((unsigned)(v >> 32));
    return lo + hi;
}

// convert 4 fp16 (as uint2) -> float4
__device__ __forceinline__ float4 h4_to_f4(uint2 u) {
    __half2 p0 = *reinterpret_cast<__half2*>(&u.x);
    __half2 p1 = *reinterpret_cast<__half2*>(&u.y);
    float2 f0 = __half22float2(p0);
    float2 f1 = __half22float2(p1);
    return make_float4(f0.x, f0.y, f1.x, f1.y);
}

// ---------------------------------------------------------------------------
// Kernel 1: per-node tiny MLP.  h1 = relu(z @ w1_l1), h2 = relu(z @ w2_l1)
// Block = 128 threads, 32 nodes. fp32 accumulate (f32x2), fp16 store.
// ---------------------------------------------------------------------------
__global__ __launch_bounds__(128) void node_mlp_kernel(
    const float* __restrict__ z,
    const float* __restrict__ w1,
    const float* __restrict__ w2,
    int n_nodes)
{
    __shared__ float zs[NPB * ZST];      // 16896 B
    __shared__ float w1T[L1D * ZST];     // [col][k], 8448 B
    __shared__ float w2T[L1D * ZST];

    const int tid = threadIdx.x;
    const int nbase = blockIdx.x * NPB;

    for (int i = tid; i < IN_DIM * L1D; i += 128) {
        int k = i >> 4, c = i & 15;
        w1T[c * ZST + k] = w1[i];
        w2T[c * ZST + k] = w2[i];
    }
    {
        const float4* z4 = (const float4*)(z + (size_t)nbase * IN_DIM);
        int nval = n_nodes - nbase; if (nval > NPB) nval = NPB;
        for (int i = tid; i < nval * (IN_DIM / 4); i += 128) {
            int r = i >> 5, q = i & 31;
            *(float4*)(zs + r * ZST + q * 4) = z4[i];
        }
    }
    __syncthreads();

    const int col  = tid & 15;
    const int slot = (tid >> 4) & 1;
    const int warp = tid >> 5;
    const int nloc0 = warp * 8 + slot * 4;

    unsigned long long a1[4][2] = {}, a2[4][2] = {};

    #pragma unroll 8
    for (int k = 0; k < IN_DIM; k += 4) {
        ulonglong2 wa = *(const ulonglong2*)(w1T + col * ZST + k);
        ulonglong2 wb = *(const ulonglong2*)(w2T + col * ZST + k);
        #pragma unroll
        for (int j = 0; j < 4; j++) {
            ulonglong2 zv = *(const ulonglong2*)(zs + (nloc0 + j) * ZST + k);
            fma_f32x2(a1[j][0], zv.x, wa.x);
            fma_f32x2(a1[j][1], zv.y, wa.y);
            fma_f32x2(a2[j][0], zv.x, wb.x);
            fma_f32x2(a2[j][1], zv.y, wb.y);
        }
    }

    #pragma unroll
    for (int j = 0; j < 4; j++) {
        int node = nbase + nloc0 + j;
        if (node < n_nodes) {
            float v1 = fmaxf(unpack_sum(a1[j][0]) + unpack_sum(a1[j][1]), 0.f);
            float v2 = fmaxf(unpack_sum(a2[j][0]) + unpack_sum(a2[j][1]), 0.f);
            g_h1h[node * L1D + col] = __float2half_rn(v1);
            g_h2h[node * L1D + col] = __float2half_rn(v2);
        }
    }
}

// ---------------------------------------------------------------------------
// Kernel 2: per-edge scoring, 4 lanes per edge, 2 edges per group-iteration.
// fp16 h gathers (8B/lane -> 32B/edge), fp32 smem weights, shfl reduce.
// ---------------------------------------------------------------------------
__global__ __launch_bounds__(256) void edge_kernel(
    const float* __restrict__ w1_l2,
    const float* __restrict__ w2_l2,
    const void* __restrict__ ei,
    const void* __restrict__ et,
    float* __restrict__ out,
    int n_edges, int n_etype)
{
    extern __shared__ float ws[];
    float* w1s = ws;
    float* w2s = ws + n_etype * WSTRIDE;
    __shared__ int s_is64;

    if (threadIdx.x < 32) {
        unsigned v = ((const unsigned*)ei)[2 * threadIdx.x + 1];
        unsigned any = __ballot_sync(0xFFFFFFFFu, v != 0u);
        if (threadIdx.x == 0) s_is64 = (any == 0u) ? 1 : 0;
    }
    for (int i = threadIdx.x; i < n_etype * 4; i += blockDim.x) {
        int r = i >> 2, q = i & 3;
        *(float4*)(w1s + r * WSTRIDE + q * 4) = ((const float4*)w1_l2)[i];
        *(float4*)(w2s + r * WSTRIDE + q * 4) = ((const float4*)w2_l2)[i];
    }
    __syncthreads();

    const int is64 = s_is64;
    const int sub = threadIdx.x & 3;
    const int lane_group = (threadIdx.x >> 2) & 7;
    const int group0 = (blockIdx.x * blockDim.x + threadIdx.x) >> 2;
    const int G = (gridDim.x * blockDim.x) >> 2;   // total groups
    const int warp_base0 = group0 - lane_group;
    const int emax = n_edges - 1;

    const long long* p64 = (const long long*)ei;
    const int*       p32 = (const int*)ei;
    const long long* t64 = (const long long*)et;
    const int*       t32 = (const int*)et;

    for (int base = warp_base0; base < n_edges; base += 2 * G) {
        int e0 = base + lane_group;
        int e1 = base + G + lane_group;
        int ec0 = e0 < n_edges ? e0 : emax;
        int ec1 = e1 < n_edges ? e1 : emax;

        int s0, d0, t0, s1, d1, t1;
        if (is64) {
            s0 = (int)__ldg(p64 + ec0);
            d0 = (int)__ldg(p64 + (size_t)n_edges + ec0);
            t0 = (int)__ldg(t64 + ec0);
            s1 = (int)__ldg(p64 + ec1);
            d1 = (int)__ldg(p64 + (size_t)n_edges + ec1);
            t1 = (int)__ldg(t64 + ec1);
        } else {
            s0 = __ldg(p32 + ec0);
            d0 = __ldg(p32 + (size_t)n_edges + ec0);
            t0 = __ldg(t32 + ec0);
            s1 = __ldg(p32 + ec1);
            d1 = __ldg(p32 + (size_t)n_edges + ec1);
            t1 = __ldg(t32 + ec1);
        }

        // issue all 4 gathers before converting/consuming
        uint2 ra0 = *(const uint2*)(g_h1h + s0 * L1D + sub * 4);
        uint2 rb0 = *(const uint2*)(g_h2h + d0 * L1D + sub * 4);
        uint2 ra1 = *(const uint2*)(g_h1h + s1 * L1D + sub * 4);
        uint2 rb1 = *(const uint2*)(g_h2h + d1 * L1D + sub * 4);

        float4 u0 = *(const float4*)(w1s + t0 * WSTRIDE + sub * 4);
        float4 v0 = *(const float4*)(w2s + t0 * WSTRIDE + sub * 4);
        float4 u1 = *(const float4*)(w1s + t1 * WSTRIDE + sub * 4);
        float4 v1 = *(const float4*)(w2s + t1 * WSTRIDE + sub * 4);

        float4 a0 = h4_to_f4(ra0), b0 = h4_to_f4(rb0);
        float4 a1 = h4_to_f4(ra1), b1 = h4_to_f4(rb1);

        float acc0, acc1;
        acc0 = a0.x * u0.x;
        acc0 = fmaf(a0.y, u0.y, acc0);
        acc0 = fmaf(a0.z, u0.z, acc0);
        acc0 = fmaf(a0.w, u0.w, acc0);
        acc0 = fmaf(b0.x, v0.x, acc0);
        acc0 = fmaf(b0.y, v0.y, acc0);
        acc0 = fmaf(b0.z, v0.z, acc0);
        acc0 = fmaf(b0.w, v0.w, acc0);

        acc1 = a1.x * u1.x;
        acc1 = fmaf(a1.y, u1.y, acc1);
        acc1 = fmaf(a1.z, u1.z, acc1);
        acc1 = fmaf(a1.w, u1.w, acc1);
        acc1 = fmaf(b1.x, v1.x, acc1);
        acc1 = fmaf(b1.y, v1.y, acc1);
        acc1 = fmaf(b1.z, v1.z, acc1);
        acc1 = fmaf(b1.w, v1.w, acc1);

        acc0 += __shfl_xor_sync(0xFFFFFFFFu, acc0, 1);
        acc1 += __shfl_xor_sync(0xFFFFFFFFu, acc1, 1);
        acc0 += __shfl_xor_sync(0xFFFFFFFFu, acc0, 2);
        acc1 += __shfl_xor_sync(0xFFFFFFFFu, acc1, 2);

        if (sub == 0) {
            if (e0 < n_edges) out[e0] = 1.f / (1.f + __expf(-acc0));
            if (e1 < n_edges) out[e1] = 1.f / (1.f + __expf(-acc1));
        }
    }
}

// ---------------------------------------------------------------------------
// Launch. Inputs (metadata order): z, w1_l1, w1_l2, w2_l1, w2_l2,
// edge_index [2,E], edge_type [E].  Output: float32 [E].
// ---------------------------------------------------------------------------
extern "C" void kernel_launch(void* const* d_in, const int* in_sizes, int n_in,
                              void* d_out, int out_size) {
    const float* z     = (const float*)d_in[0];
    const float* w1_l1 = (const float*)d_in[1];
    const float* w1_l2 = (const float*)d_in[2];
    const float* w2_l1 = (const float*)d_in[3];
    const float* w2_l2 = (const float*)d_in[4];
    const void*  ei    = d_in[5];
    const void*  et    = d_in[6];
    float* out = (float*)d_out;

    int n_nodes = in_sizes[0] / IN_DIM;
    int n_etype = in_sizes[2] / L1D;
    int n_edges = out_size;

    int nb1 = (n_nodes + NPB - 1) / NPB;
    node_mlp_kernel<<<nb1, 128>>>(z, w1_l1, w2_l1, n_nodes);

    size_t smem = (size_t)2 * n_etype * WSTRIDE * sizeof(float);
    edge_kernel<<<1036, 256, smem>>>(w1_l2, w2_l2, ei, et, out, n_edges, n_etype);
}

// round 10
// speedup vs baseline: 1.7110x; 1.1979x over previous
#include <cuda_runtime.h>
#include <cuda_fp16.h>

#define L1D 16
#define IN_DIM 128
#define MAXN 65536
#define ZST 132      // padded smem row stride in node MLP
#define NPB 32       // nodes per block in node_mlp
#define WROW 40      // combined weight row stride in halves (32 data + 8 pad)

// Scratch: node hidden activations in fp16 (allowed: __device__ globals)
__device__ __align__(16) __half g_h1h[MAXN * L1D];
__device__ __align__(16) __half g_h2h[MAXN * L1D];

// packed f32x2 fma: d = a*b + d
__device__ __forceinline__ void fma_f32x2(unsigned long long& d,
                                          unsigned long long a,
                                          unsigned long long b) {
    asm("fma.rn.f32x2 %0, %1, %2, %0;" : "+l"(d) : "l"(a), "l"(b));
}
__device__ __forceinline__ float unpack_sum(unsigned long long v) {
    float lo = __uint_as_float((unsigned)(v & 0xFFFFFFFFu));
    float hi = __uint_as_float((unsigned)(v >> 32));
    return lo + hi;
}

// ---------------------------------------------------------------------------
// Kernel 1: per-node tiny MLP.  h1 = relu(z @ w1_l1), h2 = relu(z @ w2_l1)
// Block = 128 threads, 32 nodes. fp32 accumulate (f32x2), fp16 store.
// ---------------------------------------------------------------------------
__global__ __launch_bounds__(128) void node_mlp_kernel(
    const float* __restrict__ z,
    const float* __restrict__ w1,
    const float* __restrict__ w2,
    int n_nodes)
{
    __shared__ float zs[NPB * ZST];      // 16896 B
    __shared__ float w1T[L1D * ZST];     // [col][k], 8448 B
    __shared__ float w2T[L1D * ZST];

    const int tid = threadIdx.x;
    const int nbase = blockIdx.x * NPB;

    for (int i = tid; i < IN_DIM * L1D; i += 128) {
        int k = i >> 4, c = i & 15;
        w1T[c * ZST + k] = w1[i];
        w2T[c * ZST + k] = w2[i];
    }
    {
        const float4* z4 = (const float4*)(z + (size_t)nbase * IN_DIM);
        int nval = n_nodes - nbase; if (nval > NPB) nval = NPB;
        for (int i = tid; i < nval * (IN_DIM / 4); i += 128) {
            int r = i >> 5, q = i & 31;
            *(float4*)(zs + r * ZST + q * 4) = z4[i];
        }
    }
    __syncthreads();

    const int col  = tid & 15;
    const int slot = (tid >> 4) & 1;
    const int warp = tid >> 5;
    const int nloc0 = warp * 8 + slot * 4;

    unsigned long long a1[4][2] = {}, a2[4][2] = {};

    #pragma unroll 8
    for (int k = 0; k < IN_DIM; k += 4) {
        ulonglong2 wa = *(const ulonglong2*)(w1T + col * ZST + k);
        ulonglong2 wb = *(const ulonglong2*)(w2T + col * ZST + k);
        #pragma unroll
        for (int j = 0; j < 4; j++) {
            ulonglong2 zv = *(const ulonglong2*)(zs + (nloc0 + j) * ZST + k);
            fma_f32x2(a1[j][0], zv.x, wa.x);
            fma_f32x2(a1[j][1], zv.y, wa.y);
            fma_f32x2(a2[j][0], zv.x, wb.x);
            fma_f32x2(a2[j][1], zv.y, wb.y);
        }
    }

    #pragma unroll
    for (int j = 0; j < 4; j++) {
        int node = nbase + nloc0 + j;
        if (node < n_nodes) {
            float v1 = fmaxf(unpack_sum(a1[j][0]) + unpack_sum(a1[j][1]), 0.f);
            float v2 = fmaxf(unpack_sum(a2[j][0]) + unpack_sum(a2[j][1]), 0.f);
            g_h1h[node * L1D + col] = __float2half_rn(v1);
            g_h2h[node * L1D + col] = __float2half_rn(v2);
        }
    }
}

// ---------------------------------------------------------------------------
// Kernel 2: per-edge scoring, 4 lanes per edge, 2 edges per group-iteration.
// Combined fp16 weight rows in smem: wc[t] = [w1_l2[t]|w2_l2[t]] (32 halves,
// stride WROW). Lane sub: sub<2 -> h1[s] half 0/1, sub>=2 -> h2[d] half 0/1.
// ONE gather LDG.128 + ONE LDS.128 per edge. fp32 accumulate.
// ---------------------------------------------------------------------------
__global__ __launch_bounds__(256) void edge_kernel(
    const float* __restrict__ w1_l2,
    const float* __restrict__ w2_l2,
    const void* __restrict__ ei,
    const void* __restrict__ et,
    float* __restrict__ out,
    int n_edges, int n_etype)
{
    extern __shared__ __half wch[];   // [n_etype][WROW]
    __shared__ int s_is64;

    if (threadIdx.x < 32) {
        unsigned v = ((const unsigned*)ei)[2 * threadIdx.x + 1];
        unsigned any = __ballot_sync(0xFFFFFFFFu, v != 0u);
        if (threadIdx.x == 0) s_is64 = (any == 0u) ? 1 : 0;
    }
    // stage combined fp16 rows: chunk i = (t, q): q<2 from w1, else w2
    for (int i = threadIdx.x; i < n_etype * 4; i += blockDim.x) {
        int t = i >> 2, q = i & 3;
        const float4* src = (q < 2) ? (const float4*)w1_l2 : (const float4*)w2_l2;
        int qq = q & 1;
        float4 fa = src[t * 4 + qq * 2];
        float4 fb = src[t * 4 + qq * 2 + 1];
        __half2 h0 = __float22half2_rn(make_float2(fa.x, fa.y));
        __half2 h1 = __float22half2_rn(make_float2(fa.z, fa.w));
        __half2 h2 = __float22half2_rn(make_float2(fb.x, fb.y));
        __half2 h3 = __float22half2_rn(make_float2(fb.z, fb.w));
        uint4 pk = make_uint4(*(unsigned*)&h0, *(unsigned*)&h1,
                              *(unsigned*)&h2, *(unsigned*)&h3);
        *(uint4*)(wch + t * WROW + q * 8) = pk;
    }
    __syncthreads();

    const int is64 = s_is64;
    const int sub = threadIdx.x & 3;
    const int lane_group = (threadIdx.x >> 2) & 7;
    const int group0 = (blockIdx.x * blockDim.x + threadIdx.x) >> 2;
    const int G = (gridDim.x * blockDim.x) >> 2;   // total groups
    const int warp_base0 = group0 - lane_group;
    const int emax = n_edges - 1;

    const __half* htab = (sub < 2) ? g_h1h : g_h2h;
    const int hq = (sub & 1) * 8;

    const long long* p64 = (const long long*)ei;
    const int*       p32 = (const int*)ei;
    const long long* t64 = (const long long*)et;
    const int*       t32 = (const int*)et;
    const size_t doff = (size_t)n_edges;

    for (int base = warp_base0; base < n_edges; base += 2 * G) {
        int e0 = base + lane_group;
        int e1 = base + G + lane_group;
        int ec0 = e0 < n_edges ? e0 : emax;
        int ec1 = e1 < n_edges ? e1 : emax;

        int n0, t0, n1, t1;   // n = gathered node id for THIS lane (s or d)
        if (is64) {
            long long s0 = __ldg(p64 + ec0), d0 = __ldg(p64 + doff + ec0);
            long long s1 = __ldg(p64 + ec1), d1 = __ldg(p64 + doff + ec1);
            t0 = (int)__ldg(t64 + ec0);
            t1 = (int)__ldg(t64 + ec1);
            n0 = (int)(sub < 2 ? s0 : d0);
            n1 = (int)(sub < 2 ? s1 : d1);
        } else {
            int s0 = __ldg(p32 + ec0), d0 = __ldg(p32 + doff + ec0);
            int s1 = __ldg(p32 + ec1), d1 = __ldg(p32 + doff + ec1);
            t0 = __ldg(t32 + ec0);
            t1 = __ldg(t32 + ec1);
            n0 = sub < 2 ? s0 : d0;
            n1 = sub < 2 ? s1 : d1;
        }

        uint4 hv0 = *(const uint4*)(htab + n0 * L1D + hq);
        uint4 hv1 = *(const uint4*)(htab + n1 * L1D + hq);
        uint4 wv0 = *(const uint4*)(wch + t0 * WROW + sub * 8);
        uint4 wv1 = *(const uint4*)(wch + t1 * WROW + sub * 8);

        float acc0 = 0.f, acc1 = 0.f;
        const unsigned* hp0 = (const unsigned*)&hv0;
        const unsigned* wp0 = (const unsigned*)&wv0;
        const unsigned* hp1 = (const unsigned*)&hv1;
        const unsigned* wp1 = (const unsigned*)&wv1;
        #pragma unroll
        for (int k = 0; k < 4; k++) {
            float2 ha = __half22float2(*(const __half2*)(hp0 + k));
            float2 wa = __half22float2(*(const __half2*)(wp0 + k));
            acc0 = fmaf(ha.x, wa.x, acc0);
            acc0 = fmaf(ha.y, wa.y, acc0);
            float2 hb = __half22float2(*(const __half2*)(hp1 + k));
            float2 wb = __half22float2(*(const __half2*)(wp1 + k));
            acc1 = fmaf(hb.x, wb.x, acc1);
            acc1 = fmaf(hb.y, wb.y, acc1);
        }

        acc0 += __shfl_xor_sync(0xFFFFFFFFu, acc0, 1);
        acc1 += __shfl_xor_sync(0xFFFFFFFFu, acc1, 1);
        acc0 += __shfl_xor_sync(0xFFFFFFFFu, acc0, 2);
        acc1 += __shfl_xor_sync(0xFFFFFFFFu, acc1, 2);

        if (sub == 0) {
            if (e0 < n_edges) out[e0] = 1.f / (1.f + __expf(-acc0));
            if (e1 < n_edges) out[e1] = 1.f / (1.f + __expf(-acc1));
        }
    }
}

// ---------------------------------------------------------------------------
// Launch. Inputs (metadata order): z, w1_l1, w1_l2, w2_l1, w2_l2,
// edge_index [2,E], edge_type [E].  Output: float32 [E].
// ---------------------------------------------------------------------------
extern "C" void kernel_launch(void* const* d_in, const int* in_sizes, int n_in,
                              void* d_out, int out_size) {
    const float* z     = (const float*)d_in[0];
    const float* w1_l1 = (const float*)d_in[1];
    const float* w1_l2 = (const float*)d_in[2];
    const float* w2_l1 = (const float*)d_in[3];
    const float* w2_l2 = (const float*)d_in[4];
    const void*  ei    = d_in[5];
    const void*  et    = d_in[6];
    float* out = (float*)d_out;

    int n_nodes = in_sizes[0] / IN_DIM;
    int n_etype = in_sizes[2] / L1D;
    int n_edges = out_size;

    int nb1 = (n_nodes + NPB - 1) / NPB;
    node_mlp_kernel<<<nb1, 128>>>(z, w1_l1, w2_l1, n_nodes);

    size_t smem = (size_t)n_etype * WROW * sizeof(__half);
    edge_kernel<<<1036, 256, smem>>>(w1_l2, w2_l2, ei, et, out, n_edges, n_etype);
}

// round 11
// speedup vs baseline: 1.7142x; 1.0019x over previous
#include <cuda_runtime.h>
#include <cuda_fp16.h>

#define L1D 16
#define IN_DIM 128
#define MAXN 65536
#define ZST 132      // padded smem row stride in node MLP
#define NPB 32       // nodes per block in node_mlp
#define WROW 40      // combined weight row stride in halves (32 data + 8 pad)

// Scratch: node hidden activations in fp16 (allowed: __device__ globals)
__device__ __align__(16) __half g_h1h[MAXN * L1D];
__device__ __align__(16) __half g_h2h[MAXN * L1D];

// packed f32x2 fma: d = a*b + d
__device__ __forceinline__ void fma_f32x2(unsigned long long& d,
                                          unsigned long long a,
                                          unsigned long long b) {
    asm("fma.rn.f32x2 %0, %1, %2, %0;" : "+l"(d) : "l"(a), "l"(b));
}
__device__ __forceinline__ float unpack_sum(unsigned long long v) {
    float lo = __uint_as_float((unsigned)(v & 0xFFFFFFFFu));
    float hi = __uint_as_float((unsigned)(v >> 32));
    return lo + hi;
}

// ---------------------------------------------------------------------------
// Kernel 1: per-node tiny MLP.  h1 = relu(z @ w1_l1), h2 = relu(z @ w2_l1)
// Block = 128 threads, 32 nodes. fp32 accumulate (f32x2), fp16 store.
// ---------------------------------------------------------------------------
__global__ __launch_bounds__(128) void node_mlp_kernel(
    const float* __restrict__ z,
    const float* __restrict__ w1,
    const float* __restrict__ w2,
    int n_nodes)
{
    __shared__ float zs[NPB * ZST];      // 16896 B
    __shared__ float w1T[L1D * ZST];     // [col][k], 8448 B
    __shared__ float w2T[L1D * ZST];

    const int tid = threadIdx.x;
    const int nbase = blockIdx.x * NPB;

    for (int i = tid; i < IN_DIM * L1D; i += 128) {
        int k = i >> 4, c = i & 15;
        w1T[c * ZST + k] = w1[i];
        w2T[c * ZST + k] = w2[i];
    }
    {
        const float4* z4 = (const float4*)(z + (size_t)nbase * IN_DIM);
        int nval = n_nodes - nbase; if (nval > NPB) nval = NPB;
        for (int i = tid; i < nval * (IN_DIM / 4); i += 128) {
            int r = i >> 5, q = i & 31;
            *(float4*)(zs + r * ZST + q * 4) = z4[i];
        }
    }
    __syncthreads();

    const int col  = tid & 15;
    const int slot = (tid >> 4) & 1;
    const int warp = tid >> 5;
    const int nloc0 = warp * 8 + slot * 4;

    unsigned long long a1[4][2] = {}, a2[4][2] = {};

    #pragma unroll 8
    for (int k = 0; k < IN_DIM; k += 4) {
        ulonglong2 wa = *(const ulonglong2*)(w1T + col * ZST + k);
        ulonglong2 wb = *(const ulonglong2*)(w2T + col * ZST + k);
        #pragma unroll
        for (int j = 0; j < 4; j++) {
            ulonglong2 zv = *(const ulonglong2*)(zs + (nloc0 + j) * ZST + k);
            fma_f32x2(a1[j][0], zv.x, wa.x);
            fma_f32x2(a1[j][1], zv.y, wa.y);
            fma_f32x2(a2[j][0], zv.x, wb.x);
            fma_f32x2(a2[j][1], zv.y, wb.y);
        }
    }

    #pragma unroll
    for (int j = 0; j < 4; j++) {
        int node = nbase + nloc0 + j;
        if (node < n_nodes) {
            float v1 = fmaxf(unpack_sum(a1[j][0]) + unpack_sum(a1[j][1]), 0.f);
            float v2 = fmaxf(unpack_sum(a2[j][0]) + unpack_sum(a2[j][1]), 0.f);
            g_h1h[node * L1D + col] = __float2half_rn(v1);
            g_h2h[node * L1D + col] = __float2half_rn(v2);
        }
    }
}

// ---------------------------------------------------------------------------
// Kernel 2: per-edge scoring, 4 lanes per edge, CONSECUTIVE edge pair
// (2p, 2p+1) per group-iteration. Role-split index loads (lane needs only
// s or d) as vector loads; combined fp16 weight rows; paired float2 store.
// ---------------------------------------------------------------------------
__global__ __launch_bounds__(256) void edge_kernel(
    const float* __restrict__ w1_l2,
    const float* __restrict__ w2_l2,
    const void* __restrict__ ei,
    const void* __restrict__ et,
    float* __restrict__ out,
    int n_edges, int n_etype)
{
    extern __shared__ __half wch[];   // [n_etype][WROW]
    __shared__ int s_is64;

    if (threadIdx.x < 32) {
        unsigned v = ((const unsigned*)ei)[2 * threadIdx.x + 1];
        unsigned any = __ballot_sync(0xFFFFFFFFu, v != 0u);
        if (threadIdx.x == 0) s_is64 = (any == 0u) ? 1 : 0;
    }
    // stage combined fp16 rows: chunk i = (t, q): q<2 from w1, else w2
    for (int i = threadIdx.x; i < n_etype * 4; i += blockDim.x) {
        int t = i >> 2, q = i & 3;
        const float4* src = (q < 2) ? (const float4*)w1_l2 : (const float4*)w2_l2;
        int qq = q & 1;
        float4 fa = src[t * 4 + qq * 2];
        float4 fb = src[t * 4 + qq * 2 + 1];
        __half2 h0 = __float22half2_rn(make_float2(fa.x, fa.y));
        __half2 h1 = __float22half2_rn(make_float2(fa.z, fa.w));
        __half2 h2 = __float22half2_rn(make_float2(fb.x, fb.y));
        __half2 h3 = __float22half2_rn(make_float2(fb.z, fb.w));
        uint4 pk = make_uint4(*(unsigned*)&h0, *(unsigned*)&h1,
                              *(unsigned*)&h2, *(unsigned*)&h3);
        *(uint4*)(wch + t * WROW + q * 8) = pk;
    }
    __syncthreads();

    const int is64 = s_is64;
    const bool even = (n_edges & 1) == 0;
    const int sub = threadIdx.x & 3;
    const int lane_group = (threadIdx.x >> 2) & 7;
    const int group0 = (blockIdx.x * blockDim.x + threadIdx.x) >> 2;
    const int G = (gridDim.x * blockDim.x) >> 2;
    const int warp_base0 = group0 - lane_group;
    const int npairs = (n_edges + 1) >> 1;
    const int pmax = npairs - 1;
    const int emax = n_edges - 1;

    const __half* htab = (sub < 2) ? g_h1h : g_h2h;
    const int hq = (sub & 1) * 8;
    const size_t noff = (sub < 2) ? 0 : (size_t)n_edges;

    const long long* p64 = (const long long*)ei + noff;
    const int*       p32 = (const int*)ei + noff;
    const long long* t64 = (const long long*)et;
    const int*       t32 = (const int*)et;

    for (int base = warp_base0; base < npairs; base += G) {
        int pp = base + lane_group;
        int pc = pp < npairs ? pp : pmax;
        int e0 = 2 * pc;

        int nA, nB, tA, tB;
        if (is64) {
            if (even) {
                longlong2 nv = *(const longlong2*)(p64 + e0);
                longlong2 tv = *(const longlong2*)(t64 + e0);
                nA = (int)nv.x; nB = (int)nv.y;
                tA = (int)tv.x; tB = (int)tv.y;
            } else {
                int eB = (e0 + 1 < n_edges) ? e0 + 1 : emax;
                nA = (int)__ldg(p64 + e0); nB = (int)__ldg(p64 + eB);
                tA = (int)__ldg(t64 + e0); tB = (int)__ldg(t64 + eB);
            }
        } else {
            if (even) {
                int2 nv = *(const int2*)(p32 + e0);
                int2 tv = *(const int2*)(t32 + e0);
                nA = nv.x; nB = nv.y;
                tA = tv.x; tB = tv.y;
            } else {
                int eB = (e0 + 1 < n_edges) ? e0 + 1 : emax;
                nA = __ldg(p32 + e0); nB = __ldg(p32 + eB);
                tA = __ldg(t32 + e0); tB = __ldg(t32 + eB);
            }
        }

        uint4 hv0 = *(const uint4*)(htab + nA * L1D + hq);
        uint4 hv1 = *(const uint4*)(htab + nB * L1D + hq);
        uint4 wv0 = *(const uint4*)(wch + tA * WROW + sub * 8);
        uint4 wv1 = *(const uint4*)(wch + tB * WROW + sub * 8);

        float acc0 = 0.f, acc1 = 0.f;
        const unsigned* hp0 = (const unsigned*)&hv0;
        const unsigned* wp0 = (const unsigned*)&wv0;
        const unsigned* hp1 = (const unsigned*)&hv1;
        const unsigned* wp1 = (const unsigned*)&wv1;
        #pragma unroll
        for (int k = 0; k < 4; k++) {
            float2 ha = __half22float2(*(const __half2*)(hp0 + k));
            float2 wa = __half22float2(*(const __half2*)(wp0 + k));
            acc0 = fmaf(ha.x, wa.x, acc0);
            acc0 = fmaf(ha.y, wa.y, acc0);
            float2 hb = __half22float2(*(const __half2*)(hp1 + k));
            float2 wb = __half22float2(*(const __half2*)(wp1 + k));
            acc1 = fmaf(hb.x, wb.x, acc1);
            acc1 = fmaf(hb.y, wb.y, acc1);
        }

        acc0 += __shfl_xor_sync(0xFFFFFFFFu, acc0, 1);
        acc1 += __shfl_xor_sync(0xFFFFFFFFu, acc1, 1);
        acc0 += __shfl_xor_sync(0xFFFFFFFFu, acc0, 2);
        acc1 += __shfl_xor_sync(0xFFFFFFFFu, acc1, 2);

        if (sub == 0) {
            float o0 = 1.f / (1.f + __expf(-acc0));
            float o1 = 1.f / (1.f + __expf(-acc1));
            if (e0 + 1 < n_edges) {
                *(float2*)(out + e0) = make_float2(o0, o1);
            } else {
                out[e0] = o0;
            }
        }
    }
}

// ---------------------------------------------------------------------------
// Launch. Inputs (metadata order): z, w1_l1, w1_l2, w2_l1, w2_l2,
// edge_index [2,E], edge_type [E].  Output: float32 [E].
// ---------------------------------------------------------------------------
extern "C" void kernel_launch(void* const* d_in, const int* in_sizes, int n_in,
                              void* d_out, int out_size) {
    const float* z     = (const float*)d_in[0];
    const float* w1_l1 = (const float*)d_in[1];
    const float* w1_l2 = (const float*)d_in[2];
    const float* w2_l1 = (const float*)d_in[3];
    const float* w2_l2 = (const float*)d_in[4];
    const void*  ei    = d_in[5];
    const void*  et    = d_in[6];
    float* out = (float*)d_out;

    int n_nodes = in_sizes[0] / IN_DIM;
    int n_etype = in_sizes[2] / L1D;
    int n_edges = out_size;

    int nb1 = (n_nodes + NPB - 1) / NPB;
    node_mlp_kernel<<<nb1, 128>>>(z, w1_l1, w2_l1, n_nodes);

    size_t smem = (size_t)n_etype * WROW * sizeof(__half);
    edge_kernel<<<1036, 256, smem>>>(w1_l2, w2_l2, ei, et, out, n_edges, n_etype);
}